// round 7
// baseline (speedup 1.0000x reference)
#include <cuda_runtime.h>
#include <cuda_bf16.h>

#define B_BAGS 16384
#define OUT_STRIDE 288

// Exclusive offsets per table: g_off[t*(B_BAGS+1) + b]
__device__ int g_off[4 * (B_BAGS + 1)];

// ---------------------------------------------------------------------------
// Scan: one block per table, 1024 threads, 16 lens per thread.
// ---------------------------------------------------------------------------
__global__ void scan_kernel(const int* __restrict__ l0, const int* __restrict__ l1,
                            const int* __restrict__ l2, const int* __restrict__ l3) {
    int t = blockIdx.x;
    const int* lens = (t == 0) ? l0 : (t == 1) ? l1 : (t == 2) ? l2 : l3;
    __shared__ int warp_sums[32];
    int i = threadIdx.x;
    int lane = i & 31;
    int wid = i >> 5;

    int local[16];
    int s = 0;
#pragma unroll
    for (int j = 0; j < 16; j++) {
        local[j] = __ldg(lens + i * 16 + j);
        s += local[j];
    }

    int inc = s;
#pragma unroll
    for (int d = 1; d < 32; d <<= 1) {
        int v = __shfl_up_sync(0xffffffffu, inc, d);
        if (lane >= d) inc += v;
    }
    if (lane == 31) warp_sums[wid] = inc;
    __syncthreads();

    if (wid == 0) {
        int ws = warp_sums[lane];
        int winc = ws;
#pragma unroll
        for (int d = 1; d < 32; d <<= 1) {
            int v = __shfl_up_sync(0xffffffffu, winc, d);
            if (lane >= d) winc += v;
        }
        warp_sums[lane] = winc - ws;
    }
    __syncthreads();

    int run = warp_sums[wid] + (inc - s);
    int* off = g_off + t * (B_BAGS + 1);
#pragma unroll
    for (int j = 0; j < 16; j++) {
        off[i * 16 + j] = run;
        run += local[j];
    }
    if (i == 1023) off[B_BAGS] = run;
}

// ---------------------------------------------------------------------------
// Pooling helpers. STREAM=true -> evict-first loads (single-use tables).
// ---------------------------------------------------------------------------
template <int VEC, bool STREAM>
__device__ __forceinline__ void vload(float* d, const float* __restrict__ p) {
    if constexpr (VEC == 1) {
        d[0] = STREAM ? __ldcs(p) : __ldg(p);
    } else if constexpr (VEC == 2) {
        float2 v = STREAM ? __ldcs(reinterpret_cast<const float2*>(p))
                          : __ldg(reinterpret_cast<const float2*>(p));
        d[0] = v.x; d[1] = v.y;
    } else {
        float4 v = STREAM ? __ldcs(reinterpret_cast<const float4*>(p))
                          : __ldg(reinterpret_cast<const float4*>(p));
        d[0] = v.x; d[1] = v.y; d[2] = v.z; d[3] = v.w;
    }
}

template <int VEC>
__device__ __forceinline__ void vstore(float* __restrict__ p, const float* d) {
    if constexpr (VEC == 1) {
        __stcs(p, d[0]);
    } else if constexpr (VEC == 2) {
        float2 v; v.x = d[0]; v.y = d[1];
        __stcs(reinterpret_cast<float2*>(p), v);
    } else {
        float4 v; v.x = d[0]; v.y = d[1]; v.z = d[2]; v.w = d[3];
        __stcs(reinterpret_cast<float4*>(p), v);
    }
}

template <int VEC, bool STREAM>
__device__ __forceinline__ void pool_bag(const float* __restrict__ W,
                                         const int* __restrict__ ids, int len,
                                         float* __restrict__ o, int lane) {
    constexpr int DIM = 32 * VEC;
    const int col = lane * VEC;
    float acc[VEC];
#pragma unroll
    for (int v = 0; v < VEC; v++) acc[v] = 0.f;

    int k = 0;
    for (; k + 4 <= len; k += 4) {
        int id0 = __ldcs(ids + k + 0);
        int id1 = __ldcs(ids + k + 1);
        int id2 = __ldcs(ids + k + 2);
        int id3 = __ldcs(ids + k + 3);
        float t0[VEC], t1[VEC], t2[VEC], t3[VEC];
        vload<VEC, STREAM>(t0, W + (size_t)id0 * DIM + col);
        vload<VEC, STREAM>(t1, W + (size_t)id1 * DIM + col);
        vload<VEC, STREAM>(t2, W + (size_t)id2 * DIM + col);
        vload<VEC, STREAM>(t3, W + (size_t)id3 * DIM + col);
#pragma unroll
        for (int v = 0; v < VEC; v++) acc[v] += (t0[v] + t1[v]) + (t2[v] + t3[v]);
    }
    for (; k < len; k++) {
        float tv[VEC];
        vload<VEC, STREAM>(tv, W + (size_t)__ldcs(ids + k) * DIM + col);
#pragma unroll
        for (int v = 0; v < VEC; v++) acc[v] += tv[v];
    }
    vstore<VEC>(o + col, acc);
}

// ---------------------------------------------------------------------------
// Schedule: Phase A (warps 0..40959) = all T1/T2 bags interleaved with 25% of
// T0/T3 at a 4:1 cached:stream ratio — enough streaming to soak spare DRAM
// bandwidth while W1/W2 stay L2-resident. Phase B (warps 40960..65535) = the
// remaining 75% of T0/T3, pure DRAM streaming.
// ---------------------------------------------------------------------------
__global__ void __launch_bounds__(256)
pool_kernel(const float* __restrict__ W0, const float* __restrict__ W1,
            const float* __restrict__ W2, const float* __restrict__ W3,
            const int* __restrict__ I0, const int* __restrict__ I1,
            const int* __restrict__ I2, const int* __restrict__ I3,
            float* __restrict__ out) {
    int g = blockIdx.x * (blockDim.x >> 5) + (threadIdx.x >> 5);
    int lane = threadIdx.x & 31;

    int t, bag;
    if (g < 40960) {
        int q = g / 5;
        int r = g - q * 5;
        if (r < 4) {                 // cached leg: T1/T2, all 32768 bags
            int idx = q * 4 + r;     // [0, 32768)
            t = (idx & 1) ? 2 : 1;
            bag = idx >> 1;
        } else {                     // metered stream leg: first 4096 bags of T0/T3
            t = (q & 1) ? 3 : 0;
            bag = q >> 1;            // [0, 4096)
        }
    } else {                         // pure stream phase: bags 4096..16383 of T0/T3
        int h = g - 40960;           // [0, 24576)
        t = (h & 1) ? 3 : 0;
        bag = 4096 + (h >> 1);
    }

    const int* off = g_off + t * (B_BAGS + 1);
    int o0 = off[bag];
    int len = off[bag + 1] - o0;
    float* obase = out + (size_t)bag * OUT_STRIDE;

    switch (t) {
        case 0: pool_bag<2, true >(W0, I0 + o0, len, obase + 0, lane); break;   // dim 64, stream
        case 1: pool_bag<4, false>(W1, I1 + o0, len, obase + 64, lane); break;  // dim 128, cache
        case 2: pool_bag<1, false>(W2, I2 + o0, len, obase + 192, lane); break; // dim 32, cache
        case 3: pool_bag<2, true >(W3, I3 + o0, len, obase + 224, lane); break; // dim 64, stream
    }
}

// ---------------------------------------------------------------------------
extern "C" void kernel_launch(void* const* d_in, const int* in_sizes, int n_in,
                              void* d_out, int out_size) {
    const float *W0, *W1, *W2, *W3;
    const int *I0, *I1, *I2, *I3, *L0, *L1, *L2, *L3;

    if (in_sizes[2] == B_BAGS) {
        // interleaved (W0,ids0,lens0,W1,...)
        W0 = (const float*)d_in[0]; I0 = (const int*)d_in[1];  L0 = (const int*)d_in[2];
        W1 = (const float*)d_in[3]; I1 = (const int*)d_in[4];  L1 = (const int*)d_in[5];
        W2 = (const float*)d_in[6]; I2 = (const int*)d_in[7];  L2 = (const int*)d_in[8];
        W3 = (const float*)d_in[9]; I3 = (const int*)d_in[10]; L3 = (const int*)d_in[11];
    } else {
        // grouped (reference signature order)
        W0 = (const float*)d_in[0]; W1 = (const float*)d_in[1];
        W2 = (const float*)d_in[2]; W3 = (const float*)d_in[3];
        I0 = (const int*)d_in[4];   I1 = (const int*)d_in[5];
        I2 = (const int*)d_in[6];   I3 = (const int*)d_in[7];
        L0 = (const int*)d_in[8];   L1 = (const int*)d_in[9];
        L2 = (const int*)d_in[10];  L3 = (const int*)d_in[11];
    }

    float* out = (float*)d_out;

    scan_kernel<<<4, 1024>>>(L0, L1, L2, L3);
    pool_kernel<<<8192, 256>>>(W0, W1, W2, W3, I0, I1, I2, I3, out);
}

// round 8
// speedup vs baseline: 1.1163x; 1.1163x over previous
#include <cuda_runtime.h>
#include <cuda_bf16.h>

#define B_BAGS 16384
#define OUT_STRIDE 288
#define OFF_STRIDE 16400  // per-table offset stride, 16B-aligned (16400*4 % 16 == 0)

// Exclusive offsets per table: g_off[t*OFF_STRIDE + b], entries [0..B_BAGS]
__device__ __align__(16) int g_off[4 * OFF_STRIDE];

// ---------------------------------------------------------------------------
// Scan: one block per table, 1024 threads, 16 lens per thread.
// Fully vectorized int4 loads/stores (dense bytes -> coalesced-equivalent
// wavefront count), two-level warp-shuffle scan (2 barriers).
// ---------------------------------------------------------------------------
__global__ void scan_kernel(const int* __restrict__ l0, const int* __restrict__ l1,
                            const int* __restrict__ l2, const int* __restrict__ l3) {
    int t = blockIdx.x;
    const int* lens = (t == 0) ? l0 : (t == 1) ? l1 : (t == 2) ? l2 : l3;
    __shared__ int warp_sums[32];
    int i = threadIdx.x;
    int lane = i & 31;
    int wid = i >> 5;

    // 16 contiguous lens per thread via 4x int4
    const int4* lens4 = reinterpret_cast<const int4*>(lens) + i * 4;
    int4 a0 = __ldg(lens4 + 0);
    int4 a1 = __ldg(lens4 + 1);
    int4 a2 = __ldg(lens4 + 2);
    int4 a3 = __ldg(lens4 + 3);

    int local[16] = {a0.x, a0.y, a0.z, a0.w, a1.x, a1.y, a1.z, a1.w,
                     a2.x, a2.y, a2.z, a2.w, a3.x, a3.y, a3.z, a3.w};
    int s = 0;
#pragma unroll
    for (int j = 0; j < 16; j++) s += local[j];

    int inc = s;
#pragma unroll
    for (int d = 1; d < 32; d <<= 1) {
        int v = __shfl_up_sync(0xffffffffu, inc, d);
        if (lane >= d) inc += v;
    }
    if (lane == 31) warp_sums[wid] = inc;
    __syncthreads();

    if (wid == 0) {
        int ws = warp_sums[lane];
        int winc = ws;
#pragma unroll
        for (int d = 1; d < 32; d <<= 1) {
            int v = __shfl_up_sync(0xffffffffu, winc, d);
            if (lane >= d) winc += v;
        }
        warp_sums[lane] = winc - ws;
    }
    __syncthreads();

    int run = warp_sums[wid] + (inc - s);  // exclusive prefix for this thread's chunk
    int* off = g_off + t * OFF_STRIDE;

    int o[16];
#pragma unroll
    for (int j = 0; j < 16; j++) {
        o[j] = run;
        run += local[j];
    }
    int4* off4 = reinterpret_cast<int4*>(off + i * 16);
    off4[0] = make_int4(o[0], o[1], o[2], o[3]);
    off4[1] = make_int4(o[4], o[5], o[6], o[7]);
    off4[2] = make_int4(o[8], o[9], o[10], o[11]);
    off4[3] = make_int4(o[12], o[13], o[14], o[15]);
    if (i == 1023) off[B_BAGS] = run;
}

// ---------------------------------------------------------------------------
// Pooling helpers. STREAM=true -> evict-first loads (single-use tables).
// ---------------------------------------------------------------------------
template <int VEC, bool STREAM>
__device__ __forceinline__ void vload(float* d, const float* __restrict__ p) {
    if constexpr (VEC == 1) {
        d[0] = STREAM ? __ldcs(p) : __ldg(p);
    } else if constexpr (VEC == 2) {
        float2 v = STREAM ? __ldcs(reinterpret_cast<const float2*>(p))
                          : __ldg(reinterpret_cast<const float2*>(p));
        d[0] = v.x; d[1] = v.y;
    } else {
        float4 v = STREAM ? __ldcs(reinterpret_cast<const float4*>(p))
                          : __ldg(reinterpret_cast<const float4*>(p));
        d[0] = v.x; d[1] = v.y; d[2] = v.z; d[3] = v.w;
    }
}

template <int VEC>
__device__ __forceinline__ void vstore(float* __restrict__ p, const float* d) {
    if constexpr (VEC == 1) {
        __stcs(p, d[0]);
    } else if constexpr (VEC == 2) {
        float2 v; v.x = d[0]; v.y = d[1];
        __stcs(reinterpret_cast<float2*>(p), v);
    } else {
        float4 v; v.x = d[0]; v.y = d[1]; v.z = d[2]; v.w = d[3];
        __stcs(reinterpret_cast<float4*>(p), v);
    }
}

template <int VEC, bool STREAM>
__device__ __forceinline__ void pool_bag(const float* __restrict__ W,
                                         const int* __restrict__ ids, int len,
                                         float* __restrict__ o, int lane) {
    constexpr int DIM = 32 * VEC;
    const int col = lane * VEC;
    float acc[VEC];
#pragma unroll
    for (int v = 0; v < VEC; v++) acc[v] = 0.f;

    int k = 0;
    for (; k + 4 <= len; k += 4) {
        int id0 = __ldcs(ids + k + 0);
        int id1 = __ldcs(ids + k + 1);
        int id2 = __ldcs(ids + k + 2);
        int id3 = __ldcs(ids + k + 3);
        float t0[VEC], t1[VEC], t2[VEC], t3[VEC];
        vload<VEC, STREAM>(t0, W + (size_t)id0 * DIM + col);
        vload<VEC, STREAM>(t1, W + (size_t)id1 * DIM + col);
        vload<VEC, STREAM>(t2, W + (size_t)id2 * DIM + col);
        vload<VEC, STREAM>(t3, W + (size_t)id3 * DIM + col);
#pragma unroll
        for (int v = 0; v < VEC; v++) acc[v] += (t0[v] + t1[v]) + (t2[v] + t3[v]);
    }
    for (; k < len; k++) {
        float tv[VEC];
        vload<VEC, STREAM>(tv, W + (size_t)__ldcs(ids + k) * DIM + col);
#pragma unroll
        for (int v = 0; v < VEC; v++) acc[v] += tv[v];
    }
    vstore<VEC>(o + col, acc);
}

// ---------------------------------------------------------------------------
// R3 windowed schedule (proven best): waves process one table at a time.
// L2-resident tables (W1: 51MB, W2: 64MB) first, streaming tables last.
// W1+W2 = 115MB of 126MB L2 -> knife-edge residency; any concurrent streaming
// thrashes it (measured R5/R7), so strict windows.
// ---------------------------------------------------------------------------
__global__ void __launch_bounds__(256)
pool_kernel(const float* __restrict__ W0, const float* __restrict__ W1,
            const float* __restrict__ W2, const float* __restrict__ W3,
            const int* __restrict__ I0, const int* __restrict__ I1,
            const int* __restrict__ I2, const int* __restrict__ I3,
            float* __restrict__ out) {
    int g = blockIdx.x * (blockDim.x >> 5) + (threadIdx.x >> 5);
    int lane = threadIdx.x & 31;

    int group = g >> 14;          // 16384 warps per table group
    int bag = g & (B_BAGS - 1);
    if (group >= 4) return;
    // group order: T1, T2, T0, T3
    int t = (group == 0) ? 1 : (group == 1) ? 2 : (group == 2) ? 0 : 3;

    const int* off = g_off + t * OFF_STRIDE;
    int o0 = off[bag];
    int len = off[bag + 1] - o0;
    float* obase = out + (size_t)bag * OUT_STRIDE;

    switch (t) {
        case 0: pool_bag<2, true >(W0, I0 + o0, len, obase + 0, lane); break;   // dim 64, stream
        case 1: pool_bag<4, false>(W1, I1 + o0, len, obase + 64, lane); break;  // dim 128, cache
        case 2: pool_bag<1, false>(W2, I2 + o0, len, obase + 192, lane); break; // dim 32, cache
        case 3: pool_bag<2, true >(W3, I3 + o0, len, obase + 224, lane); break; // dim 64, stream
    }
}

// ---------------------------------------------------------------------------
extern "C" void kernel_launch(void* const* d_in, const int* in_sizes, int n_in,
                              void* d_out, int out_size) {
    const float *W0, *W1, *W2, *W3;
    const int *I0, *I1, *I2, *I3, *L0, *L1, *L2, *L3;

    if (in_sizes[2] == B_BAGS) {
        // interleaved (W0,ids0,lens0,W1,...)
        W0 = (const float*)d_in[0]; I0 = (const int*)d_in[1];  L0 = (const int*)d_in[2];
        W1 = (const float*)d_in[3]; I1 = (const int*)d_in[4];  L1 = (const int*)d_in[5];
        W2 = (const float*)d_in[6]; I2 = (const int*)d_in[7];  L2 = (const int*)d_in[8];
        W3 = (const float*)d_in[9]; I3 = (const int*)d_in[10]; L3 = (const int*)d_in[11];
    } else {
        // grouped (reference signature order)
        W0 = (const float*)d_in[0]; W1 = (const float*)d_in[1];
        W2 = (const float*)d_in[2]; W3 = (const float*)d_in[3];
        I0 = (const int*)d_in[4];   I1 = (const int*)d_in[5];
        I2 = (const int*)d_in[6];   I3 = (const int*)d_in[7];
        L0 = (const int*)d_in[8];   L1 = (const int*)d_in[9];
        L2 = (const int*)d_in[10];  L3 = (const int*)d_in[11];
    }

    float* out = (float*)d_out;

    scan_kernel<<<4, 1024>>>(L0, L1, L2, L3);
    pool_kernel<<<8192, 256>>>(W0, W1, W2, W3, I0, I1, I2, I3, out);
}

// round 9
// speedup vs baseline: 1.1480x; 1.0284x over previous
#include <cuda_runtime.h>
#include <cuda_bf16.h>

#define B_BAGS 16384
#define OUT_STRIDE 288
#define OFF_STRIDE 16400  // per-table offset stride, 16B-aligned (16400*4 % 16 == 0)

// Exclusive offsets per table: g_off[t*OFF_STRIDE + b], entries [0..B_BAGS]
__device__ __align__(16) int g_off[4 * OFF_STRIDE];

// ---------------------------------------------------------------------------
// Scan: one block per table, 1024 threads, 16 lens per thread.
// Fully vectorized int4 loads/stores, two-level warp-shuffle scan.
// ---------------------------------------------------------------------------
__global__ void scan_kernel(const int* __restrict__ l0, const int* __restrict__ l1,
                            const int* __restrict__ l2, const int* __restrict__ l3) {
    int t = blockIdx.x;
    const int* lens = (t == 0) ? l0 : (t == 1) ? l1 : (t == 2) ? l2 : l3;
    __shared__ int warp_sums[32];
    int i = threadIdx.x;
    int lane = i & 31;
    int wid = i >> 5;

    const int4* lens4 = reinterpret_cast<const int4*>(lens) + i * 4;
    int4 a0 = __ldg(lens4 + 0);
    int4 a1 = __ldg(lens4 + 1);
    int4 a2 = __ldg(lens4 + 2);
    int4 a3 = __ldg(lens4 + 3);

    int local[16] = {a0.x, a0.y, a0.z, a0.w, a1.x, a1.y, a1.z, a1.w,
                     a2.x, a2.y, a2.z, a2.w, a3.x, a3.y, a3.z, a3.w};
    int s = 0;
#pragma unroll
    for (int j = 0; j < 16; j++) s += local[j];

    int inc = s;
#pragma unroll
    for (int d = 1; d < 32; d <<= 1) {
        int v = __shfl_up_sync(0xffffffffu, inc, d);
        if (lane >= d) inc += v;
    }
    if (lane == 31) warp_sums[wid] = inc;
    __syncthreads();

    if (wid == 0) {
        int ws = warp_sums[lane];
        int winc = ws;
#pragma unroll
        for (int d = 1; d < 32; d <<= 1) {
            int v = __shfl_up_sync(0xffffffffu, winc, d);
            if (lane >= d) winc += v;
        }
        warp_sums[lane] = winc - ws;
    }
    __syncthreads();

    int run = warp_sums[wid] + (inc - s);
    int* off = g_off + t * OFF_STRIDE;

    int o[16];
#pragma unroll
    for (int j = 0; j < 16; j++) {
        o[j] = run;
        run += local[j];
    }
    int4* off4 = reinterpret_cast<int4*>(off + i * 16);
    off4[0] = make_int4(o[0], o[1], o[2], o[3]);
    off4[1] = make_int4(o[4], o[5], o[6], o[7]);
    off4[2] = make_int4(o[8], o[9], o[10], o[11]);
    off4[3] = make_int4(o[12], o[13], o[14], o[15]);
    if (i == 1023) off[B_BAGS] = run;
}

// ---------------------------------------------------------------------------
// Pooling helpers. STREAM=true -> evict-first loads.
// ---------------------------------------------------------------------------
template <int VEC, bool STREAM>
__device__ __forceinline__ void vload(float* d, const float* __restrict__ p) {
    if constexpr (VEC == 1) {
        d[0] = STREAM ? __ldcs(p) : __ldg(p);
    } else if constexpr (VEC == 2) {
        float2 v = STREAM ? __ldcs(reinterpret_cast<const float2*>(p))
                          : __ldg(reinterpret_cast<const float2*>(p));
        d[0] = v.x; d[1] = v.y;
    } else {
        float4 v = STREAM ? __ldcs(reinterpret_cast<const float4*>(p))
                          : __ldg(reinterpret_cast<const float4*>(p));
        d[0] = v.x; d[1] = v.y; d[2] = v.z; d[3] = v.w;
    }
}

template <int VEC>
__device__ __forceinline__ void vstore(float* __restrict__ p, const float* d) {
    if constexpr (VEC == 1) {
        __stcs(p, d[0]);
    } else if constexpr (VEC == 2) {
        float2 v; v.x = d[0]; v.y = d[1];
        __stcs(reinterpret_cast<float2*>(p), v);
    } else {
        float4 v; v.x = d[0]; v.y = d[1]; v.z = d[2]; v.w = d[3];
        __stcs(reinterpret_cast<float4*>(p), v);
    }
}

template <int VEC, bool STREAM>
__device__ __forceinline__ void pool_bag(const float* __restrict__ W,
                                         const int* __restrict__ ids, int len,
                                         float* __restrict__ o, int lane) {
    constexpr int DIM = 32 * VEC;
    const int col = lane * VEC;
    float acc[VEC];
#pragma unroll
    for (int v = 0; v < VEC; v++) acc[v] = 0.f;

    int k = 0;
    for (; k + 4 <= len; k += 4) {
        int id0 = __ldcs(ids + k + 0);
        int id1 = __ldcs(ids + k + 1);
        int id2 = __ldcs(ids + k + 2);
        int id3 = __ldcs(ids + k + 3);
        float t0[VEC], t1[VEC], t2[VEC], t3[VEC];
        vload<VEC, STREAM>(t0, W + (size_t)id0 * DIM + col);
        vload<VEC, STREAM>(t1, W + (size_t)id1 * DIM + col);
        vload<VEC, STREAM>(t2, W + (size_t)id2 * DIM + col);
        vload<VEC, STREAM>(t3, W + (size_t)id3 * DIM + col);
#pragma unroll
        for (int v = 0; v < VEC; v++) acc[v] += (t0[v] + t1[v]) + (t2[v] + t3[v]);
    }
    for (; k < len; k++) {
        float tv[VEC];
        vload<VEC, STREAM>(tv, W + (size_t)__ldcs(ids + k) * DIM + col);
#pragma unroll
        for (int v = 0; v < VEC; v++) acc[v] += tv[v];
    }
    vstore<VEC>(o + col, acc);
}

// ---------------------------------------------------------------------------
// Windowed schedule (proven best): waves process one table at a time.
// L2-resident tables (W1: 51MB, W2: 64MB) first; T0/T3 phase runs after, so
// nothing in L2 needs protecting then -> default caching for T0/T3 captures
// their ~1.46x intra-phase row reuse (~259K re-read rows/table x 256B).
// ---------------------------------------------------------------------------
__global__ void __launch_bounds__(256)
pool_kernel(const float* __restrict__ W0, const float* __restrict__ W1,
            const float* __restrict__ W2, const float* __restrict__ W3,
            const int* __restrict__ I0, const int* __restrict__ I1,
            const int* __restrict__ I2, const int* __restrict__ I3,
            float* __restrict__ out) {
    int g = blockIdx.x * (blockDim.x >> 5) + (threadIdx.x >> 5);
    int lane = threadIdx.x & 31;

    int group = g >> 14;          // 16384 warps per table group
    int bag = g & (B_BAGS - 1);
    if (group >= 4) return;
    // group order: T1, T2, T0, T3
    int t = (group == 0) ? 1 : (group == 1) ? 2 : (group == 2) ? 0 : 3;

    const int* off = g_off + t * OFF_STRIDE;
    int o0 = off[bag];
    int len = off[bag + 1] - o0;
    float* obase = out + (size_t)bag * OUT_STRIDE;

    switch (t) {
        case 0: pool_bag<2, false>(W0, I0 + o0, len, obase + 0, lane); break;   // dim 64, cached (phase B)
        case 1: pool_bag<4, false>(W1, I1 + o0, len, obase + 64, lane); break;  // dim 128, cached
        case 2: pool_bag<1, false>(W2, I2 + o0, len, obase + 192, lane); break; // dim 32, cached
        case 3: pool_bag<2, false>(W3, I3 + o0, len, obase + 224, lane); break; // dim 64, cached (phase B)
    }
}

// ---------------------------------------------------------------------------
extern "C" void kernel_launch(void* const* d_in, const int* in_sizes, int n_in,
                              void* d_out, int out_size) {
    const float *W0, *W1, *W2, *W3;
    const int *I0, *I1, *I2, *I3, *L0, *L1, *L2, *L3;

    if (in_sizes[2] == B_BAGS) {
        // interleaved (W0,ids0,lens0,W1,...)
        W0 = (const float*)d_in[0]; I0 = (const int*)d_in[1];  L0 = (const int*)d_in[2];
        W1 = (const float*)d_in[3]; I1 = (const int*)d_in[4];  L1 = (const int*)d_in[5];
        W2 = (const float*)d_in[6]; I2 = (const int*)d_in[7];  L2 = (const int*)d_in[8];
        W3 = (const float*)d_in[9]; I3 = (const int*)d_in[10]; L3 = (const int*)d_in[11];
    } else {
        // grouped (reference signature order)
        W0 = (const float*)d_in[0]; W1 = (const float*)d_in[1];
        W2 = (const float*)d_in[2]; W3 = (const float*)d_in[3];
        I0 = (const int*)d_in[4];   I1 = (const int*)d_in[5];
        I2 = (const int*)d_in[6];   I3 = (const int*)d_in[7];
        L0 = (const int*)d_in[8];   L1 = (const int*)d_in[9];
        L2 = (const int*)d_in[10];  L3 = (const int*)d_in[11];
    }

    float* out = (float*)d_out;

    scan_kernel<<<4, 1024>>>(L0, L1, L2, L3);
    pool_kernel<<<8192, 256>>>(W0, W1, W2, W3, I0, I1, I2, I3, out);
}